// round 8
// baseline (speedup 1.0000x reference)
#include <cuda_runtime.h>

// ScorePredictor: 3x DistMult edge scoring.
// score[e] = clip( sum_d head[src[e],d] * rel[d] * tail[dst[e],d], 0, 1 )
//
// Pipeline (graph-capturable, allocation-free):
//  1. counting sort of each edge list by one endpoint; scatter emits packed
//     int4 records (key, other, edge) so the score kernel's metadata read is
//     one coalesced load.
//  2. ONE fused score kernel; each warp handles 16 consecutive SORTED edges,
//     k-chunk outer loop. Per k-iter: rel chunk loaded once (amortized /16),
//     head chunk reloaded only on key change (~2.5 loads/16 edges), tails in
//     two schedulable batches of 8 (MLP >= 8/warp).

#define D_DIM 2048
#define WARPS_PER_BLOCK 8
#define THREADS_PER_BLOCK (WARPS_PER_BLOCK * 32)
#define EDGES_PER_WARP 16
#define EDGES_PER_BLOCK (WARPS_PER_BLOCK * EDGES_PER_WARP)

#define MAX_BINS 32768
#define MAX_E    131072

__device__ int  g_hist[3][MAX_BINS];
__device__ int4 g_edge[3][MAX_E];    // (key, other, edge, pad)

// ---------------- sort: zero / hist / scan / scatter ----------------

__global__ void zero_hist_kernel() {
    int i = blockIdx.x * blockDim.x + threadIdx.x;
    if (i < 3 * MAX_BINS) ((int*)g_hist)[i] = 0;
}

__global__ void hist_kernel(const int* __restrict__ k0,   // ddi_src
                            const int* __restrict__ k1,   // dpi_dst
                            const int* __restrict__ k2,   // ppi_src
                            int E) {
    int i = blockIdx.x * blockDim.x + threadIdx.x;
    if (i >= 3 * E) return;
    int p = i / E, e = i - p * E;
    int key = (p == 0) ? __ldg(k0 + e) : (p == 1) ? __ldg(k1 + e) : __ldg(k2 + e);
    atomicAdd(&g_hist[p][key], 1);
}

__global__ void scan_kernel(int nbins0, int nbins12) {
    const int p = blockIdx.x;           // one block per phase
    const int nbins = (p == 0) ? nbins0 : nbins12;
    int* h = g_hist[p];
    const int T = 1024;
    const int t = threadIdx.x;
    __shared__ int buf[2][1024];

    int chunk = (nbins + T - 1) / T;
    int start = t * chunk;
    int end   = min(start + chunk, nbins);

    int s = 0;
    for (int i = start; i < end; ++i) s += h[i];
    buf[0][t] = s;
    __syncthreads();

    int src = 0;
    for (int off = 1; off < T; off <<= 1) {
        int v = buf[src][t];
        if (t >= off) v += buf[src][t - off];
        buf[src ^ 1][t] = v;
        src ^= 1;
        __syncthreads();
    }

    int base = (t == 0) ? 0 : buf[src][t - 1];
    int run = base;
    for (int i = start; i < end; ++i) {
        int v = h[i];
        h[i] = run;
        run += v;
    }
}

__global__ void scatter_kernel(const int* __restrict__ s0, const int* __restrict__ d0,
                               const int* __restrict__ s1, const int* __restrict__ d1,
                               const int* __restrict__ s2, const int* __restrict__ d2,
                               int E) {
    int i = blockIdx.x * blockDim.x + threadIdx.x;
    if (i >= 3 * E) return;
    int p = i / E, e = i - p * E;
    // grouping key: ddi by src, dpi by dst (protein side), ppi by src
    int key, other;
    if (p == 0)      { key = __ldg(s0 + e); other = __ldg(d0 + e); }
    else if (p == 1) { key = __ldg(d1 + e); other = __ldg(s1 + e); }
    else             { key = __ldg(s2 + e); other = __ldg(d2 + e); }
    int pos = atomicAdd(&g_hist[p][key], 1);
    g_edge[p][pos] = make_int4(key, other, e, 0);
}

// ---------------- fused score ----------------

__global__ __launch_bounds__(THREADS_PER_BLOCK, 2)
void edge_score_fused(
    const float* __restrict__ x_drug,
    const float* __restrict__ x_prot,
    const float* __restrict__ rel_ddi,
    const float* __restrict__ rel_dpi,
    float*       __restrict__ out,
    int E, int blocks_per_phase)
{
    const int phase = blockIdx.x / blocks_per_phase;
    const int blk   = blockIdx.x - phase * blocks_per_phase;

    // Table binding: sorted-side table (heads), random-side table (tails).
    const float* xs;  const float* xr;  const float* rel;  float* o;
    if (phase == 0)      { xs = x_drug; xr = x_drug; rel = rel_ddi; o = out; }
    else if (phase == 1) { xs = x_prot; xr = x_drug; rel = rel_dpi; o = out + E; }
    else                 { xs = x_prot; xr = x_prot; rel = rel_dpi; o = out + 2 * E; }
    const int4* recs = g_edge[phase];

    const int warp = threadIdx.x >> 5;
    const int lane = threadIdx.x & 31;
    const int base = (blk * WARPS_PER_BLOCK + warp) * EDGES_PER_WARP;
    if (base >= E) return;

    // Lanes 0..15 fetch packed edge records; broadcast via shuffles.
    int pos = base + lane;
    if (pos >= E) pos = E - 1;              // duplicate last edge (same output)
    int my_s = 0, my_d = 0, my_edge = 0;
    if (lane < EDGES_PER_WARP) {
        int4 r = __ldg(recs + pos);
        my_s = r.x; my_d = r.y; my_edge = r.z;
    }

    int s[EDGES_PER_WARP], dI[EDGES_PER_WARP];
    #pragma unroll
    for (int e = 0; e < EDGES_PER_WARP; ++e) {
        s[e]  = __shfl_sync(0xffffffffu, my_s, e);
        dI[e] = __shfl_sync(0xffffffffu, my_d, e);
    }

    float acc[EDGES_PER_WARP];
    #pragma unroll
    for (int e = 0; e < EDGES_PER_WARP; ++e) acc[e] = 0.0f;

    // 16 k-chunks of float4 per lane. Tails in two schedulable batches of 8.
    #pragma unroll 2
    for (int k = 0; k < D_DIM / (32 * 4); ++k) {
        const int idx = (k * 32 + lane) * 4;
        const float4 r = __ldg(reinterpret_cast<const float4*>(rel + idx));

        #pragma unroll
        for (int half = 0; half < 2; ++half) {
            const int eb = half * 8;

            float4 t[8];
            #pragma unroll
            for (int e = 0; e < 8; ++e)
                t[e] = __ldg(reinterpret_cast<const float4*>(
                           xr + (size_t)dI[eb + e] * D_DIM + idx));

            float4 hr;   // head*rel; reload only on key change (warp-uniform)
            #pragma unroll
            for (int e = 0; e < 8; ++e) {
                const int ee = eb + e;
                if (ee == 0 || s[ee] != s[ee - 1]) {
                    float4 h = __ldg(reinterpret_cast<const float4*>(
                                   xs + (size_t)s[ee] * D_DIM + idx));
                    hr.x = h.x * r.x; hr.y = h.y * r.y;
                    hr.z = h.z * r.z; hr.w = h.w * r.w;
                } else if (e == 0) {
                    // re-derive hr at batch boundary when key continues
                    float4 h = __ldg(reinterpret_cast<const float4*>(
                                   xs + (size_t)s[ee] * D_DIM + idx));
                    hr.x = h.x * r.x; hr.y = h.y * r.y;
                    hr.z = h.z * r.z; hr.w = h.w * r.w;
                }
                acc[ee] = fmaf(hr.x, t[e].x, acc[ee]);
                acc[ee] = fmaf(hr.y, t[e].y, acc[ee]);
                acc[ee] = fmaf(hr.z, t[e].z, acc[ee]);
                acc[ee] = fmaf(hr.w, t[e].w, acc[ee]);
            }
        }
    }

    // Reduce and write each edge's score.
    #pragma unroll
    for (int e = 0; e < EDGES_PER_WARP; ++e) {
        float a = acc[e];
        #pragma unroll
        for (int off = 16; off > 0; off >>= 1)
            a += __shfl_xor_sync(0xffffffffu, a, off);
        const int edge_e = __shfl_sync(0xffffffffu, my_edge, e);
        if (lane == 0)
            o[edge_e] = fminf(fmaxf(a, 0.0f), 1.0f);
    }
}

// ---------------- launch ----------------

extern "C" void kernel_launch(void* const* d_in, const int* in_sizes, int n_in,
                              void* d_out, int out_size)
{
    const float* x_drug  = (const float*)d_in[0];
    const float* x_prot  = (const float*)d_in[1];
    const float* rel_ddi = (const float*)d_in[2];
    const float* rel_dpi = (const float*)d_in[3];
    const int*   ddi_src = (const int*)d_in[4];
    const int*   ddi_dst = (const int*)d_in[5];
    const int*   dpi_src = (const int*)d_in[6];
    const int*   dpi_dst = (const int*)d_in[7];
    const int*   ppi_src = (const int*)d_in[8];
    const int*   ppi_dst = (const int*)d_in[9];
    float* out = (float*)d_out;

    const int E      = in_sizes[4];
    const int N_DRUG = in_sizes[0] / D_DIM;
    const int N_PROT = in_sizes[1] / D_DIM;

    zero_hist_kernel<<<(3 * MAX_BINS + 255) / 256, 256>>>();
    hist_kernel<<<(3 * E + 255) / 256, 256>>>(ddi_src, dpi_dst, ppi_src, E);
    scan_kernel<<<3, 1024>>>(N_DRUG, N_PROT);
    scatter_kernel<<<(3 * E + 255) / 256, 256>>>(
        ddi_src, ddi_dst, dpi_src, dpi_dst, ppi_src, ppi_dst, E);

    const int bpp = (E + EDGES_PER_BLOCK - 1) / EDGES_PER_BLOCK;

    edge_score_fused<<<3 * bpp, THREADS_PER_BLOCK>>>(
        x_drug, x_prot, rel_ddi, rel_dpi, out, E, bpp);
}

// round 9
// speedup vs baseline: 1.3449x; 1.3449x over previous
#include <cuda_runtime.h>

// ScorePredictor: 3x DistMult edge scoring.
// score[e] = clip( sum_d head[src[e],d] * rel[d] * tail[dst[e],d], 0, 1 )
//
// Pipeline (graph-capturable, allocation-free):
//  1. counting sort of each edge list by one endpoint; scatter emits packed
//     int4 records (key, other, edge) -> score kernel metadata is ONE
//     coalesced load.
//  2. ONE fused score kernel; each warp handles 8 consecutive SORTED edges
//     (EPW=8: fits the register budget, no spills — EPW=16 spilled and lost
//     30%), k-chunk outer loop. Per k-iter: rel chunk loaded once, head chunk
//     reloaded only on key change, all 8 tail loads batched (MLP=8/warp).

#define D_DIM 2048
#define WARPS_PER_BLOCK 8
#define THREADS_PER_BLOCK (WARPS_PER_BLOCK * 32)
#define EDGES_PER_WARP 8
#define EDGES_PER_BLOCK (WARPS_PER_BLOCK * EDGES_PER_WARP)

#define MAX_BINS 32768
#define MAX_E    131072

__device__ int  g_hist[3][MAX_BINS];
__device__ int4 g_edge[3][MAX_E];    // (key, other, edge, pad)

// ---------------- sort: zero / hist / scan / scatter ----------------

__global__ void zero_hist_kernel() {
    int i = blockIdx.x * blockDim.x + threadIdx.x;
    if (i < 3 * MAX_BINS) ((int*)g_hist)[i] = 0;
}

__global__ void hist_kernel(const int* __restrict__ k0,   // ddi_src
                            const int* __restrict__ k1,   // dpi_dst
                            const int* __restrict__ k2,   // ppi_src
                            int E) {
    int i = blockIdx.x * blockDim.x + threadIdx.x;
    if (i >= 3 * E) return;
    int p = i / E, e = i - p * E;
    int key = (p == 0) ? __ldg(k0 + e) : (p == 1) ? __ldg(k1 + e) : __ldg(k2 + e);
    atomicAdd(&g_hist[p][key], 1);
}

__global__ void scan_kernel(int nbins0, int nbins12) {
    const int p = blockIdx.x;           // one block per phase
    const int nbins = (p == 0) ? nbins0 : nbins12;
    int* h = g_hist[p];
    const int T = 1024;
    const int t = threadIdx.x;
    __shared__ int buf[2][1024];

    int chunk = (nbins + T - 1) / T;
    int start = t * chunk;
    int end   = min(start + chunk, nbins);

    int s = 0;
    for (int i = start; i < end; ++i) s += h[i];
    buf[0][t] = s;
    __syncthreads();

    int src = 0;
    for (int off = 1; off < T; off <<= 1) {
        int v = buf[src][t];
        if (t >= off) v += buf[src][t - off];
        buf[src ^ 1][t] = v;
        src ^= 1;
        __syncthreads();
    }

    int base = (t == 0) ? 0 : buf[src][t - 1];
    int run = base;
    for (int i = start; i < end; ++i) {
        int v = h[i];
        h[i] = run;
        run += v;
    }
}

__global__ void scatter_kernel(const int* __restrict__ s0, const int* __restrict__ d0,
                               const int* __restrict__ s1, const int* __restrict__ d1,
                               const int* __restrict__ s2, const int* __restrict__ d2,
                               int E) {
    int i = blockIdx.x * blockDim.x + threadIdx.x;
    if (i >= 3 * E) return;
    int p = i / E, e = i - p * E;
    // grouping key: ddi by src, dpi by dst (protein side), ppi by src
    int key, other;
    if (p == 0)      { key = __ldg(s0 + e); other = __ldg(d0 + e); }
    else if (p == 1) { key = __ldg(d1 + e); other = __ldg(s1 + e); }
    else             { key = __ldg(s2 + e); other = __ldg(d2 + e); }
    int pos = atomicAdd(&g_hist[p][key], 1);
    g_edge[p][pos] = make_int4(key, other, e, 0);
}

// ---------------- fused score ----------------

__global__ __launch_bounds__(THREADS_PER_BLOCK, 3)
void edge_score_fused(
    const float* __restrict__ x_drug,
    const float* __restrict__ x_prot,
    const float* __restrict__ rel_ddi,
    const float* __restrict__ rel_dpi,
    float*       __restrict__ out,
    int E, int blocks_per_phase)
{
    const int phase = blockIdx.x / blocks_per_phase;
    const int blk   = blockIdx.x - phase * blocks_per_phase;

    // Table binding: sorted-side table (heads), random-side table (tails).
    const float* xs;  const float* xr;  const float* rel;  float* o;
    if (phase == 0)      { xs = x_drug; xr = x_drug; rel = rel_ddi; o = out; }
    else if (phase == 1) { xs = x_prot; xr = x_drug; rel = rel_dpi; o = out + E; }
    else                 { xs = x_prot; xr = x_prot; rel = rel_dpi; o = out + 2 * E; }
    const int4* recs = g_edge[phase];

    const int warp = threadIdx.x >> 5;
    const int lane = threadIdx.x & 31;
    const int base = (blk * WARPS_PER_BLOCK + warp) * EDGES_PER_WARP;
    if (base >= E) return;

    // Lanes 0..7 fetch packed edge records; broadcast via shuffles.
    int pos = base + lane;
    if (pos >= E) pos = E - 1;              // duplicate last edge (same output)
    int my_s = 0, my_d = 0, my_edge = 0;
    if (lane < EDGES_PER_WARP) {
        int4 r = __ldg(recs + pos);
        my_s = r.x; my_d = r.y; my_edge = r.z;
    }

    int s[EDGES_PER_WARP], dI[EDGES_PER_WARP];
    #pragma unroll
    for (int e = 0; e < EDGES_PER_WARP; ++e) {
        s[e]  = __shfl_sync(0xffffffffu, my_s, e);
        dI[e] = __shfl_sync(0xffffffffu, my_d, e);
    }

    float acc[EDGES_PER_WARP];
    #pragma unroll
    for (int e = 0; e < EDGES_PER_WARP; ++e) acc[e] = 0.0f;

    // 16 k-chunks of float4 per lane. Batch all 8 independent tail loads
    // before the FMA block so ptxas issues them back-to-back (MLP=8).
    #pragma unroll 2
    for (int k = 0; k < D_DIM / (32 * 4); ++k) {
        const int idx = (k * 32 + lane) * 4;

        float4 t[EDGES_PER_WARP];
        #pragma unroll
        for (int e = 0; e < EDGES_PER_WARP; ++e)
            t[e] = __ldg(reinterpret_cast<const float4*>(
                       xr + (size_t)dI[e] * D_DIM + idx));

        const float4 r = __ldg(reinterpret_cast<const float4*>(rel + idx));

        float4 hr;   // head chunk pre-multiplied by rel; reload on key change
        #pragma unroll
        for (int e = 0; e < EDGES_PER_WARP; ++e) {
            if (e == 0 || s[e] != s[e - 1]) {   // warp-uniform branch
                float4 h = __ldg(reinterpret_cast<const float4*>(
                               xs + (size_t)s[e] * D_DIM + idx));
                hr.x = h.x * r.x; hr.y = h.y * r.y;
                hr.z = h.z * r.z; hr.w = h.w * r.w;
            }
            acc[e] = fmaf(hr.x, t[e].x, acc[e]);
            acc[e] = fmaf(hr.y, t[e].y, acc[e]);
            acc[e] = fmaf(hr.z, t[e].z, acc[e]);
            acc[e] = fmaf(hr.w, t[e].w, acc[e]);
        }
    }

    // Reduce and write each edge's score.
    #pragma unroll
    for (int e = 0; e < EDGES_PER_WARP; ++e) {
        float a = acc[e];
        #pragma unroll
        for (int off = 16; off > 0; off >>= 1)
            a += __shfl_xor_sync(0xffffffffu, a, off);
        const int edge_e = __shfl_sync(0xffffffffu, my_edge, e);
        if (lane == 0)
            o[edge_e] = fminf(fmaxf(a, 0.0f), 1.0f);
    }
}

// ---------------- launch ----------------

extern "C" void kernel_launch(void* const* d_in, const int* in_sizes, int n_in,
                              void* d_out, int out_size)
{
    const float* x_drug  = (const float*)d_in[0];
    const float* x_prot  = (const float*)d_in[1];
    const float* rel_ddi = (const float*)d_in[2];
    const float* rel_dpi = (const float*)d_in[3];
    const int*   ddi_src = (const int*)d_in[4];
    const int*   ddi_dst = (const int*)d_in[5];
    const int*   dpi_src = (const int*)d_in[6];
    const int*   dpi_dst = (const int*)d_in[7];
    const int*   ppi_src = (const int*)d_in[8];
    const int*   ppi_dst = (const int*)d_in[9];
    float* out = (float*)d_out;

    const int E      = in_sizes[4];
    const int N_DRUG = in_sizes[0] / D_DIM;
    const int N_PROT = in_sizes[1] / D_DIM;

    zero_hist_kernel<<<(3 * MAX_BINS + 255) / 256, 256>>>();
    hist_kernel<<<(3 * E + 255) / 256, 256>>>(ddi_src, dpi_dst, ppi_src, E);
    scan_kernel<<<3, 1024>>>(N_DRUG, N_PROT);
    scatter_kernel<<<(3 * E + 255) / 256, 256>>>(
        ddi_src, ddi_dst, dpi_src, dpi_dst, ppi_src, ppi_dst, E);

    const int bpp = (E + EDGES_PER_BLOCK - 1) / EDGES_PER_BLOCK;

    edge_score_fused<<<3 * bpp, THREADS_PER_BLOCK>>>(
        x_drug, x_prot, rel_ddi, rel_dpi, out, E, bpp);
}